// round 14
// baseline (speedup 1.0000x reference)
#include <cuda_runtime.h>
#include <cstdint>

// LengthRegulator, fused, cp.async-staged:
// ys[b, f, :] = xs[b, i, :] where cum[b,i-1] <= f < cum[b,i], else 0.
//
// Per 32-frame block: pair-sum shuffle scan (validated R13) -> frame->row map
// -> run-length dedup (warp 0) -> ALL distinct rows staged to SMEM with
// 16B cp.async (max MLP, one latency wait per block) -> warps store frames
// from SMEM with streaming STG.128.

#define BATCH   8
#define TIN     512
#define TOUT    4096
#define DIM4    96                  // 384/4 float4 per row
#define FPB     32                  // frames per block
#define THREADS 256                 // 8 warps
#define FPW     4                   // frames per warp

static __device__ __forceinline__ uint32_t smem_u32(const void* p) {
    uint32_t a;
    asm("{ .reg .u64 t; cvta.to.shared.u64 t, %1; cvt.u32.u64 %0, t; }"
        : "=r"(a) : "l"(p));
    return a;
}

__global__ __launch_bounds__(THREADS)
void lr_fused(const float4* __restrict__ xs,
              const int* __restrict__ ds,
              float4* __restrict__ out)
{
    extern __shared__ __align__(16) float4 s_buf[];   // FPB*DIM4 = 48KB
    __shared__ int s_wsum[8];
    __shared__ int s_map[FPB];      // frame -> source row (-1 = zero)
    __shared__ int s_slot[FPB];     // frame -> staged slot (-1 = zero)
    __shared__ int s_rowof[FPB];    // slot -> source row
    __shared__ int s_nruns;

    const int b      = blockIdx.x;
    const int frame0 = blockIdx.y * FPB;
    const int tid    = threadIdx.x;
    const int lane   = tid & 31;
    const int wid    = tid >> 5;

    // ---- pair-sum scan: thread t owns ds rows 2t, 2t+1 (validated R13) ----
    const int2 dd = ((const int2*)(ds + b * TIN))[tid];
    int v = dd.x + dd.y;
#pragma unroll
    for (int off = 1; off < 32; off <<= 1) {
        int n = __shfl_up_sync(0xffffffffu, v, off);
        if (lane >= off) v += n;
    }
    if (lane == 31) s_wsum[wid] = v;
    if (tid < FPB)  s_map[tid] = -1;
    __syncthreads();

    if (wid == 0 && lane < 8) {
        int w = s_wsum[lane];
#pragma unroll
        for (int off = 1; off < 8; off <<= 1) {
            int n = __shfl_up_sync(0x000000ffu, w, off);
            if (lane >= off) w += n;
        }
        s_wsum[lane] = w;
    }
    __syncthreads();

    const int cum1  = v + (wid > 0 ? s_wsum[wid - 1] : 0);
    const int cum0  = cum1 - dd.y;
    const int left0 = cum0 - dd.x;

    const int fend = frame0 + FPB;
    {
        int lo = left0 < frame0 ? frame0 : left0;
        int hi = cum0  > fend   ? fend   : cum0;
        for (int f = lo; f < hi; f++) s_map[f - frame0] = 2 * tid;
        lo = cum0 < frame0 ? frame0 : cum0;
        hi = cum1 > fend   ? fend   : cum1;
        for (int f = lo; f < hi; f++) s_map[f - frame0] = 2 * tid + 1;
    }
    __syncthreads();

    // ---- run-length dedup (warp 0): distinct rows -> slots ----
    if (wid == 0) {
        const int  m     = s_map[lane];
        const int  prevm = (lane > 0) ? s_map[lane - 1] : -2;
        const bool head  = (lane == 0) || (m != prevm);
        const uint32_t loadmask = __ballot_sync(0xffffffffu, head && m >= 0);
        const int cnt  = __popc(loadmask & ((2u << lane) - 1u));
        const int slot = (m >= 0) ? cnt - 1 : -1;
        s_slot[lane] = slot;
        if (head && m >= 0) s_rowof[slot] = m;
        if (lane == 0) s_nruns = __popc(loadmask);
    }
    __syncthreads();

    // ---- stage all distinct rows via cp.async (16B per thread-op) ----
    const float4* __restrict__ xsb = xs + (size_t)b * TIN * DIM4;
    const int n16 = s_nruns * DIM4;
    for (int i = tid; i < n16; i += THREADS) {
        const int s   = i / DIM4;
        const int off = i - s * DIM4;
        const float4* src = xsb + s_rowof[s] * DIM4 + off;
        uint32_t dst = smem_u32(s_buf + i);
        asm volatile("cp.async.cg.shared.global [%0], [%1], 16;"
                     :: "r"(dst), "l"(src) : "memory");
    }
    asm volatile("cp.async.commit_group;" ::: "memory");
    asm volatile("cp.async.wait_group 0;" ::: "memory");
    __syncthreads();

    // ---- copy: warp w owns frames [frame0 + w*FPW, +FPW), src = SMEM ----
    const int fbase = wid * FPW;
    float4* __restrict__ o =
        out + (size_t)(b * TOUT + frame0 + fbase) * DIM4 + lane;

    int prev_slot = -3;
    float4 a0 = make_float4(0.f, 0.f, 0.f, 0.f), a1 = a0, a2 = a0;
#pragma unroll
    for (int k = 0; k < FPW; k++) {
        const int slot = s_slot[fbase + k];        // warp-uniform
        if (slot != prev_slot) {
            if (slot >= 0) {
                const float4* p = s_buf + slot * DIM4;
                a0 = p[lane];
                a1 = p[lane + 32];
                a2 = p[lane + 64];
            } else {
                a0 = a1 = a2 = make_float4(0.f, 0.f, 0.f, 0.f);
            }
            prev_slot = slot;
        }
        __stcs(o + k * DIM4,      a0);
        __stcs(o + k * DIM4 + 32, a1);
        __stcs(o + k * DIM4 + 64, a2);
    }
}

extern "C" void kernel_launch(void* const* d_in, const int* in_sizes, int n_in,
                              void* d_out, int out_size)
{
    const float* xs = (const float*)d_in[0];
    const int*   ds = (const int*)d_in[1];
    float*       out = (float*)d_out;

    const int smem = FPB * DIM4 * sizeof(float4);   // 49152 B
    cudaFuncSetAttribute(lr_fused, cudaFuncAttributeMaxDynamicSharedMemorySize, smem);

    dim3 grid(BATCH, TOUT / FPB);   // 8 x 128 = 1024 blocks
    lr_fused<<<grid, THREADS, smem>>>((const float4*)xs, ds, (float4*)out);
}